// round 6
// baseline (speedup 1.0000x reference)
#include <cuda_runtime.h>
#include <cstdint>

// Problem constants (fixed shapes from setup_inputs)
#define BATCH   2
#define NPTS    110592            // 48^3
#define BN      (BATCH * NPTS)    // 221184
#define NF      256
#define NM      16
#define NCHUNK  144               // chunks per batch
#define CHUNK   768               // points per CTA (NPTS / NCHUNK)
#define TILE    128               // points per smem tile
#define TWO_PI_F 6.283185307179586f
#define INV_SQRT_N 0.0030070286f  // 1/sqrt(110592)

#define NOUT       (BATCH * NF * NM)       // 8192 complex elements
#define OUT_FLOATS (NOUT * 2)              // 16384

// Expected element counts (bind inputs by size, order-independent)
#define SZ_A   (BN * 16)          // 3,538,944
#define SZ_X   (BN * 3)           //   663,552
#define SZ_AW  (16 * 16)          //       256
#define SZ_XW  (3 * 256)          //       768

// Static device scratch (no allocation allowed)
__device__ float4 g_A4[BN * 4];                  // A scaled: 16 floats/point (14.2 MB)
__device__ float4 g_X4[BN];                      // x padded to float4        (3.5 MB)
__device__ float  g_part[NCHUNK * OUT_FLOATS];   // per-chunk partials        (9.4 MB)

// ---------- kernel 1: A = (a @ a_weights) * inv_sqrt_n ; pad x ----------
__global__ void __launch_bounds__(256) prep_kernel(const float* __restrict__ a,
                                                   const float* __restrict__ x,
                                                   const float* __restrict__ aw) {
    __shared__ float saw[256];      // a_weights (16x16), row-major [i][m]
    saw[threadIdx.x] = aw[threadIdx.x];
    __syncthreads();

    int p = blockIdx.x * 256 + threadIdx.x;   // BN = 864 * 256 exactly

    float ai[16];
#pragma unroll
    for (int i = 0; i < 16; ++i) ai[i] = a[(size_t)p * 16 + i];

    float o[16];
#pragma unroll
    for (int m = 0; m < 16; ++m) o[m] = 0.0f;
#pragma unroll
    for (int i = 0; i < 16; ++i) {
#pragma unroll
        for (int m = 0; m < 16; ++m)
            o[m] = fmaf(ai[i], saw[i * 16 + m], o[m]);
    }

    float4* dst = &g_A4[(size_t)p * 4];
#pragma unroll
    for (int j = 0; j < 4; ++j)
        dst[j] = make_float4(o[4 * j + 0] * INV_SQRT_N, o[4 * j + 1] * INV_SQRT_N,
                             o[4 * j + 2] * INV_SQRT_N, o[4 * j + 3] * INV_SQRT_N);

    const float* xp = x + (size_t)p * 3;
    g_X4[p] = make_float4(xp[0], xp[1], xp[2], 0.0f);
}

// ---------- kernel 2: fused sincos + split-K contraction ----------
// grid = (NCHUNK, BATCH), 256 threads (one per frequency f)
__global__ void __launch_bounds__(256) spectral_main(const float* __restrict__ xw) {
    const int b = blockIdx.y;
    const int f = threadIdx.x;
    const int base = b * NPTS + blockIdx.x * CHUNK;

    const float w0 = xw[f];               // x_weights is (3,256) row-major
    const float w1 = xw[NF + f];
    const float w2 = xw[2 * NF + f];

    __shared__ float4 sA[TILE * 4];
    __shared__ float4 sX[TILE];

    float accR[16], accI[16];
#pragma unroll
    for (int m = 0; m < 16; ++m) { accR[m] = 0.0f; accI[m] = 0.0f; }

    for (int t = 0; t < CHUNK; t += TILE) {
        const float4* gA = &g_A4[(size_t)(base + t) * 4];
        for (int i = threadIdx.x; i < TILE * 4; i += 256) sA[i] = gA[i];
        if (threadIdx.x < TILE) sX[threadIdx.x] = g_X4[base + t + threadIdx.x];
        __syncthreads();

#pragma unroll 2
        for (int p = 0; p < TILE; ++p) {
            float4 xv = sX[p];                                       // broadcast
            float ph = TWO_PI_F * fmaf(xv.x, w0, fmaf(xv.y, w1, xv.z * w2));
            float s, c;
            sincosf(ph, &s, &c);   // ACCURATE version this round (precision confounder removed)
#pragma unroll
            for (int j = 0; j < 4; ++j) {
                float4 v = sA[p * 4 + j];                            // A[m=4j..4j+3]
                accR[4 * j + 0] = fmaf(v.x, c, accR[4 * j + 0]);
                accR[4 * j + 1] = fmaf(v.y, c, accR[4 * j + 1]);
                accR[4 * j + 2] = fmaf(v.z, c, accR[4 * j + 2]);
                accR[4 * j + 3] = fmaf(v.w, c, accR[4 * j + 3]);
                accI[4 * j + 0] = fmaf(v.x, s, accI[4 * j + 0]);
                accI[4 * j + 1] = fmaf(v.y, s, accI[4 * j + 1]);
                accI[4 * j + 2] = fmaf(v.z, s, accI[4 * j + 2]);
                accI[4 * j + 3] = fmaf(v.w, s, accI[4 * j + 3]);
            }
        }
        __syncthreads();
    }

    // Partial for this chunk, interleaved (re,im) per (b,f,m); im = -sum(A*sin)
    float* pp = g_part + (size_t)blockIdx.x * OUT_FLOATS + ((size_t)(b * NF + f)) * NM * 2;
#pragma unroll
    for (int m = 0; m < 16; ++m) {
        pp[2 * m]     = accR[m];
        pp[2 * m + 1] = -accI[m];
    }
}

// ---------- kernel 3: deterministic reduction, PLANAR output ----------
// out[0..NOUT)      = real plane, (b,f,m) C-order
// out[NOUT..2*NOUT) = imag plane (only if write_imag)
__global__ void __launch_bounds__(256) reduce_kernel(float* __restrict__ out, int write_imag) {
    int j = blockIdx.x * 256 + threadIdx.x;   // NOUT = 32 * 256
    float sre = 0.0f, sim = 0.0f;
#pragma unroll 4
    for (int c = 0; c < NCHUNK; ++c) {
        const float* pc = g_part + (size_t)c * OUT_FLOATS;
        sre += pc[2 * j];
        sim += pc[2 * j + 1];
    }
    out[j] = sre;
    if (write_imag) out[NOUT + j] = sim;
}

extern "C" void kernel_launch(void* const* d_in, const int* in_sizes, int n_in,
                              void* d_out, int out_size) {
    // Bind inputs by element count — robust to metadata ordering.
    const float* a  = nullptr;   // (2,48,48,48,16)
    const float* x  = nullptr;   // (2,48,48,48,3)
    const float* aw = nullptr;   // (16,16)
    const float* xw = nullptr;   // (3,256)
    for (int i = 0; i < n_in; ++i) {
        switch (in_sizes[i]) {
            case SZ_A:  a  = (const float*)d_in[i]; break;
            case SZ_X:  x  = (const float*)d_in[i]; break;
            case SZ_AW: aw = (const float*)d_in[i]; break;
            case SZ_XW: xw = (const float*)d_in[i]; break;
            default: break;
        }
    }
    float* out = (float*)d_out;

    // out_size >= 16384 floats -> room for planar imag plane; otherwise the
    // buffer holds only the real part (complex downcast to float32).
    int write_imag = (out_size >= OUT_FLOATS) ? 1 : 0;

    prep_kernel<<<BN / 256, 256>>>(a, x, aw);
    dim3 grid(NCHUNK, BATCH);
    spectral_main<<<grid, 256>>>(xw);
    reduce_kernel<<<NOUT / 256, 256>>>(out, write_imag);
}

// round 7
// speedup vs baseline: 1.5845x; 1.5845x over previous
#include <cuda_runtime.h>
#include <cstdint>

// Problem constants (fixed shapes from setup_inputs)
#define BATCH   2
#define NPTS    110592            // 48^3
#define BN      (BATCH * NPTS)    // 221184
#define NF      256
#define NM      16
#define NCHUNK  144               // chunks per batch
#define CHUNK   768               // points per CTA (NPTS / NCHUNK)
#define TILE    128               // points per smem tile
#define TWO_PI_F 6.283185307179586f
#define INV_SQRT_N 0.0030070286f  // 1/sqrt(110592)

#define NOUT       (BATCH * NF * NM)       // 8192 complex elements
#define OUT_FLOATS (NOUT * 2)              // 16384

// Expected element counts (bind inputs by size, order-independent)
#define SZ_A   (BN * 16)          // 3,538,944
#define SZ_X   (BN * 3)           //   663,552
#define SZ_AW  (16 * 16)          //       256
#define SZ_XW  (3 * 256)          //       768

// Static device scratch (no allocation allowed)
__device__ float4 g_A4[BN * 4];                  // A scaled: 16 floats/point (14.2 MB)
__device__ float4 g_X4[BN];                      // x padded to float4        (3.5 MB)
// per-chunk partials: [chunk][plane(re=0,im=1)][b][f][m]
__device__ float  g_part[NCHUNK * OUT_FLOATS];

// ---------- packed f32x2 helpers (sm_100a) ----------
__device__ __forceinline__ unsigned long long pack2(float lo, float hi) {
    unsigned long long r;
    asm("mov.b64 %0, {%1, %2};" : "=l"(r) : "f"(lo), "f"(hi));
    return r;
}
__device__ __forceinline__ void unpack2(unsigned long long v, float& lo, float& hi) {
    asm("mov.b64 {%0, %1}, %2;" : "=f"(lo), "=f"(hi) : "l"(v));
}
__device__ __forceinline__ void fma2(unsigned long long& d,
                                     unsigned long long a,
                                     unsigned long long b) {
    asm("fma.rn.f32x2 %0, %1, %2, %0;" : "+l"(d) : "l"(a), "l"(b));
}

// ---------- kernel 1: A = (a @ a_weights) * inv_sqrt_n ; pad x ----------
__global__ void __launch_bounds__(256) prep_kernel(const float* __restrict__ a,
                                                   const float* __restrict__ x,
                                                   const float* __restrict__ aw) {
    __shared__ float saw[256];      // a_weights (16x16), row-major [i][m]
    saw[threadIdx.x] = aw[threadIdx.x];
    __syncthreads();

    int p = blockIdx.x * 256 + threadIdx.x;   // BN = 864 * 256 exactly

    // vectorized load of 16 input channels (64B-aligned)
    const float4* ap = (const float4*)(a + (size_t)p * 16);
    float4 v0 = ap[0], v1 = ap[1], v2 = ap[2], v3 = ap[3];
    float ai[16] = {v0.x, v0.y, v0.z, v0.w, v1.x, v1.y, v1.z, v1.w,
                    v2.x, v2.y, v2.z, v2.w, v3.x, v3.y, v3.z, v3.w};

    float o[16];
#pragma unroll
    for (int m = 0; m < 16; ++m) o[m] = 0.0f;
#pragma unroll
    for (int i = 0; i < 16; ++i) {
#pragma unroll
        for (int m = 0; m < 16; ++m)
            o[m] = fmaf(ai[i], saw[i * 16 + m], o[m]);
    }

    float4* dst = &g_A4[(size_t)p * 4];
#pragma unroll
    for (int j = 0; j < 4; ++j)
        dst[j] = make_float4(o[4 * j + 0] * INV_SQRT_N, o[4 * j + 1] * INV_SQRT_N,
                             o[4 * j + 2] * INV_SQRT_N, o[4 * j + 3] * INV_SQRT_N);

    const float* xp = x + (size_t)p * 3;
    g_X4[p] = make_float4(xp[0], xp[1], xp[2], 0.0f);
}

// ---------- kernel 2: fused fast-sincos + packed f32x2 contraction ----------
// grid = (NCHUNK, BATCH), 256 threads (one per frequency f)
__global__ void __launch_bounds__(256) spectral_main(const float* __restrict__ xw) {
    const int b = blockIdx.y;
    const int f = threadIdx.x;
    const int base = b * NPTS + blockIdx.x * CHUNK;

    // fold 2*pi into the frequency weights once
    const float W0 = TWO_PI_F * xw[f];
    const float W1 = TWO_PI_F * xw[NF + f];
    const float W2 = TWO_PI_F * xw[2 * NF + f];

    __shared__ float4 sA[TILE * 4];
    __shared__ float4 sX[TILE];

    unsigned long long accR[8], accI[8];   // (m even, m odd) pairs
#pragma unroll
    for (int k = 0; k < 8; ++k) { accR[k] = 0ull; accI[k] = 0ull; }

    for (int t = 0; t < CHUNK; t += TILE) {
        const float4* gA = &g_A4[(size_t)(base + t) * 4];
        for (int i = threadIdx.x; i < TILE * 4; i += 256) sA[i] = gA[i];
        if (threadIdx.x < TILE) sX[threadIdx.x] = g_X4[base + t + threadIdx.x];
        __syncthreads();

#pragma unroll 4
        for (int p = 0; p < TILE; ++p) {
            float4 xv = sX[p];                                       // LDS broadcast
            float ph = fmaf(xv.x, W0, fmaf(xv.y, W1, xv.z * W2));
            float s, c;
            __sincosf(ph, &s, &c);                                   // MUFU fast path
            unsigned long long cc = pack2(c, c);
            unsigned long long ss = pack2(s, s);
            const ulonglong2* Ap = (const ulonglong2*)(&sA[p * 4]);  // 16B-aligned
#pragma unroll
            for (int j = 0; j < 4; ++j) {
                ulonglong2 v = Ap[j];          // LDS.128 broadcast -> two f32x2 operands
                fma2(accR[2 * j],     v.x, cc);
                fma2(accR[2 * j + 1], v.y, cc);
                fma2(accI[2 * j],     v.x, ss);
                fma2(accI[2 * j + 1], v.y, ss);
            }
        }
        __syncthreads();
    }

    // Partials, planar within chunk: [re plane NOUT][im plane NOUT]
    const int idx = (b * NF + f) * NM;
    float* pr = g_part + (size_t)blockIdx.x * OUT_FLOATS + idx;
    float* pi = pr + NOUT;
#pragma unroll
    for (int k = 0; k < 8; ++k) {
        float r0, r1, i0, i1;
        unpack2(accR[k], r0, r1);
        unpack2(accI[k], i0, i1);
        pr[2 * k]     = r0;
        pr[2 * k + 1] = r1;
        pi[2 * k]     = -i0;          // h_im = -sum(A*sin)
        pi[2 * k + 1] = -i1;
    }
}

// ---------- kernel 3: deterministic reduction, PLANAR output ----------
// out[0..NOUT) = real plane (b,f,m); out[NOUT..2*NOUT) = imag plane (if room)
__global__ void __launch_bounds__(256) reduce_kernel(float* __restrict__ out, int write_imag) {
    int j = blockIdx.x * 256 + threadIdx.x;   // NOUT = 32 * 256
    float sre = 0.0f, sim = 0.0f;
#pragma unroll 4
    for (int c = 0; c < NCHUNK; ++c) {
        const float* pc = g_part + (size_t)c * OUT_FLOATS;
        sre += pc[j];
        sim += pc[NOUT + j];
    }
    out[j] = sre;
    if (write_imag) out[NOUT + j] = sim;
}

extern "C" void kernel_launch(void* const* d_in, const int* in_sizes, int n_in,
                              void* d_out, int out_size) {
    // Bind inputs by element count — robust to metadata ordering.
    const float* a  = nullptr;   // (2,48,48,48,16)
    const float* x  = nullptr;   // (2,48,48,48,3)
    const float* aw = nullptr;   // (16,16)
    const float* xw = nullptr;   // (3,256)
    for (int i = 0; i < n_in; ++i) {
        switch (in_sizes[i]) {
            case SZ_A:  a  = (const float*)d_in[i]; break;
            case SZ_X:  x  = (const float*)d_in[i]; break;
            case SZ_AW: aw = (const float*)d_in[i]; break;
            case SZ_XW: xw = (const float*)d_in[i]; break;
            default: break;
        }
    }
    float* out = (float*)d_out;

    int write_imag = (out_size >= OUT_FLOATS) ? 1 : 0;

    prep_kernel<<<BN / 256, 256>>>(a, x, aw);
    dim3 grid(NCHUNK, BATCH);
    spectral_main<<<grid, 256>>>(xw);
    reduce_kernel<<<NOUT / 256, 256>>>(out, write_imag);
}

// round 9
// speedup vs baseline: 2.7821x; 1.7558x over previous
#include <cuda_runtime.h>
#include <cstdint>

// ---------------- problem constants ----------------
#define BATCH   2
#define NPTS    110592            // 48^3
#define BN      (BATCH * NPTS)    // 221184
#define NF      256
#define NM      16
#define NCHUNK  144               // chunks per batch
#define CHUNK   768               // points per CTA
#define NPB     (CHUNK / 8)       // 96 point-blocks of 8
#define TWO_PI_F 6.283185307179586f
#define INV_SQRT_N 0.0030070286f  // 1/sqrt(110592)

#define NOUT       (BATCH * NF * NM)       // 8192 complex elements
#define OUT_FLOATS (NOUT * 2)              // 16384

#define SZ_A   (BN * 16)
#define SZ_X   (BN * 3)
#define SZ_AW  (16 * 16)
#define SZ_XW  (3 * 256)

// SMEM layout (floats): aw[256] | x[2304] | A[12288]  => 59392 bytes
#define SMF_AW  0
#define SMF_X   256
#define SMF_A   (256 + 2304)
#define SMEM_BYTES ((256 + 2304 + 12288) * 4)

// ---------------- device scratch (no allocation allowed) ----------------
__device__ float g_part[NCHUNK * OUT_FLOATS];   // per-chunk planar partials (9.4 MB)

// ---------------- helpers ----------------
__device__ __forceinline__ uint32_t tf32r(float f) {
    uint32_t r;
    asm("cvt.rna.tf32.f32 %0, %1;" : "=r"(r) : "f"(f));
    return r;
}
__device__ __forceinline__ void mma_tf32(float* d, const uint32_t* a, const uint32_t* b) {
    asm volatile(
        "mma.sync.aligned.m16n8k8.row.col.f32.tf32.tf32.f32 "
        "{%0,%1,%2,%3}, {%4,%5,%6,%7}, {%8,%9}, {%0,%1,%2,%3};"
        : "+f"(d[0]), "+f"(d[1]), "+f"(d[2]), "+f"(d[3])
        : "r"(a[0]), "r"(a[1]), "r"(a[2]), "r"(a[3]), "r"(b[0]), "r"(b[1]));
}

// ---------- fused kernel: stage + project + sincos + tf32 MMA ----------
// grid = (NCHUNK, BATCH), 256 threads. Warp w covers f in [w*32, w*32+32).
__global__ void __launch_bounds__(256, 2) spectral_main(const float* __restrict__ a,
                                                        const float* __restrict__ x,
                                                        const float* __restrict__ aw,
                                                        const float* __restrict__ xw) {
    extern __shared__ float sm[];
    float* s_aw = sm + SMF_AW;   // 16x16 row-major [i][m]
    float* s_x  = sm + SMF_X;    // 768 x 3 packed
    float* s_A  = sm + SMF_A;    // 768 x 16, tf32-rounded scaled coefficients

    const int tid  = threadIdx.x;
    const int lane = tid & 31;
    const int warp = tid >> 5;
    const int b    = blockIdx.y;
    const int chunk = blockIdx.x;
    const size_t pbase = (size_t)(b * NPTS + chunk * CHUNK);

    // ---- stage: aw, raw a-chunk (48KB), x-chunk (9KB), all coalesced ----
    s_aw[tid] = aw[tid];
    {
        const float4* ga = (const float4*)(a + pbase * 16);   // 3072 float4
        float4* sa4 = (float4*)s_A;
#pragma unroll
        for (int i = 0; i < 12; ++i) sa4[tid + 256 * i] = ga[tid + 256 * i];
        const float4* gx = (const float4*)(x + pbase * 3);    // 576 float4
        float4* sx4 = (float4*)s_x;
        for (int i = tid; i < 576; i += 256) sx4[i] = gx[i];
    }
    __syncthreads();

    // ---- in-place projection: A[p][m] = tf32(sum_i a[p][i]*aw[i][m] * inv_sqrt_n)
    // each thread owns rows {tid, tid+256, tid+512}: no cross-thread hazard
#pragma unroll
    for (int r = 0; r < 3; ++r) {
        int p = r * 256 + tid;
        float ai[16];
#pragma unroll
        for (int i = 0; i < 16; ++i) ai[i] = s_A[p * 16 + i];
        float o[16];
#pragma unroll
        for (int m = 0; m < 16; ++m) o[m] = 0.0f;
#pragma unroll
        for (int i = 0; i < 16; ++i)
#pragma unroll
            for (int m = 0; m < 16; ++m)
                o[m] = fmaf(ai[i], s_aw[i * 16 + m], o[m]);
#pragma unroll
        for (int m = 0; m < 16; ++m)
            s_A[p * 16 + m] = __uint_as_float(tf32r(o[m] * INV_SQRT_N));
    }
    __syncthreads();

    // ---- per-thread frequency weights (2*pi folded), 4 f's per thread ----
    const int fb = warp * 32 + (lane >> 2);      // f rows this thread owns (+8j)
    float W[4][3];
#pragma unroll
    for (int j = 0; j < 4; ++j) {
        int f = fb + 8 * j;
        W[j][0] = TWO_PI_F * xw[f];
        W[j][1] = TWO_PI_F * xw[NF + f];
        W[j][2] = TWO_PI_F * xw[2 * NF + f];
    }

    // accumulators: [ftile][mhalf][4 c-regs]
    float accR[2][2][4], accI[2][2][4];
#pragma unroll
    for (int i = 0; i < 2; ++i)
#pragma unroll
        for (int j = 0; j < 2; ++j)
#pragma unroll
            for (int k = 0; k < 4; ++k) { accR[i][j][k] = 0.0f; accI[i][j][k] = 0.0f; }

    const int kp = lane & 3;        // k-position within point-block
    const int m0 = lane >> 2;       // m channel for B fragment

    for (int pb = 0; pb < NPB; ++pb) {
        const int p0 = pb * 8 + kp;
        // x for the two points this thread owns (broadcast-friendly LDS)
        float xa0 = s_x[p0 * 3], xb0 = s_x[p0 * 3 + 1], xc0 = s_x[p0 * 3 + 2];
        float xa1 = s_x[(p0 + 4) * 3], xb1 = s_x[(p0 + 4) * 3 + 1], xc1 = s_x[(p0 + 4) * 3 + 2];

        float cv[8], sv[8];   // [j*2 + psel]
#pragma unroll
        for (int j = 0; j < 4; ++j) {
            float ph0 = fmaf(xa0, W[j][0], fmaf(xb0, W[j][1], xc0 * W[j][2]));
            float ph1 = fmaf(xa1, W[j][0], fmaf(xb1, W[j][1], xc1 * W[j][2]));
            __sincosf(ph0, &sv[2 * j], &cv[2 * j]);
            __sincosf(ph1, &sv[2 * j + 1], &cv[2 * j + 1]);
        }

        // A fragments (trig), directly in mma layout:
        // a0=(row g, k), a1=(g+8, k), a2=(g, k+4), a3=(g+8, k+4)
        uint32_t fc0[4] = { tf32r(cv[0]), tf32r(cv[2]), tf32r(cv[1]), tf32r(cv[3]) };
        uint32_t fs0[4] = { tf32r(sv[0]), tf32r(sv[2]), tf32r(sv[1]), tf32r(sv[3]) };
        uint32_t fc1[4] = { tf32r(cv[4]), tf32r(cv[6]), tf32r(cv[5]), tf32r(cv[7]) };
        uint32_t fs1[4] = { tf32r(sv[4]), tf32r(sv[6]), tf32r(sv[5]), tf32r(sv[7]) };

        // B fragments (coefficients), b0=(k, n), b1=(k+4, n); shared by all 4 MMups
        uint32_t bm0[2] = { __float_as_uint(s_A[p0 * 16 + m0]),
                            __float_as_uint(s_A[(p0 + 4) * 16 + m0]) };
        uint32_t bm8[2] = { __float_as_uint(s_A[p0 * 16 + m0 + 8]),
                            __float_as_uint(s_A[(p0 + 4) * 16 + m0 + 8]) };

        mma_tf32(accR[0][0], fc0, bm0);  mma_tf32(accR[0][1], fc0, bm8);
        mma_tf32(accI[0][0], fs0, bm0);  mma_tf32(accI[0][1], fs0, bm8);
        mma_tf32(accR[1][0], fc1, bm0);  mma_tf32(accR[1][1], fc1, bm8);
        mma_tf32(accI[1][0], fs1, bm0);  mma_tf32(accI[1][1], fs1, bm8);
    }

    // ---- epilogue: C-fragment -> planar per-chunk partials ----
    // c0=(row g, col 2k), c1=(g, 2k+1), c2=(g+8, 2k), c3=(g+8, 2k+1)
    float* basep = g_part + (size_t)chunk * OUT_FLOATS;
#pragma unroll
    for (int ft = 0; ft < 2; ++ft) {
#pragma unroll
        for (int mh = 0; mh < 2; ++mh) {
            int mcol = mh * 8 + 2 * kp;
#pragma unroll
            for (int rh = 0; rh < 2; ++rh) {
                int f = warp * 32 + ft * 16 + (lane >> 2) + rh * 8;
                size_t o = (size_t)(b * NF + f) * NM + mcol;
                float2 vr = make_float2(accR[ft][mh][2 * rh], accR[ft][mh][2 * rh + 1]);
                float2 vi = make_float2(-accI[ft][mh][2 * rh], -accI[ft][mh][2 * rh + 1]);
                *(float2*)(basep + o) = vr;              // real plane
                *(float2*)(basep + NOUT + o) = vi;       // imag plane
            }
        }
    }
}

// ---------- reduce: deterministic sum over chunks, PLANAR output ----------
__global__ void __launch_bounds__(256) reduce_kernel(float* __restrict__ out, int write_imag) {
    int j = blockIdx.x * 256 + threadIdx.x;   // NOUT = 32 * 256
    float sre = 0.0f, sim = 0.0f;
#pragma unroll 4
    for (int c = 0; c < NCHUNK; ++c) {
        const float* pc = g_part + (size_t)c * OUT_FLOATS;
        sre += pc[j];
        sim += pc[NOUT + j];
    }
    out[j] = sre;
    if (write_imag) out[NOUT + j] = sim;
}

extern "C" void kernel_launch(void* const* d_in, const int* in_sizes, int n_in,
                              void* d_out, int out_size) {
    const float* a  = nullptr;
    const float* x  = nullptr;
    const float* aw = nullptr;
    const float* xw = nullptr;
    for (int i = 0; i < n_in; ++i) {
        switch (in_sizes[i]) {
            case SZ_A:  a  = (const float*)d_in[i]; break;
            case SZ_X:  x  = (const float*)d_in[i]; break;
            case SZ_AW: aw = (const float*)d_in[i]; break;
            case SZ_XW: xw = (const float*)d_in[i]; break;
            default: break;
        }
    }
    float* out = (float*)d_out;
    int write_imag = (out_size >= OUT_FLOATS) ? 1 : 0;

    cudaFuncSetAttribute(spectral_main,
                         cudaFuncAttributeMaxDynamicSharedMemorySize, SMEM_BYTES);

    dim3 grid(NCHUNK, BATCH);
    spectral_main<<<grid, 256, SMEM_BYTES>>>(a, x, aw, xw);
    reduce_kernel<<<NOUT / 256, 256>>>(out, write_imag);
}

// round 10
// speedup vs baseline: 3.1348x; 1.1268x over previous
#include <cuda_runtime.h>
#include <cstdint>

// ---------------- problem constants ----------------
#define BATCH   2
#define NPTS    110592            // 48^3
#define BN      (BATCH * NPTS)    // 221184
#define NF      256
#define NM      16
#define NCHUNK  144               // chunks per batch
#define CHUNK   768               // points per CTA
#define NPB     (CHUNK / 8)       // 96 point-blocks of 8
#define TWO_PI_F 6.283185307179586f
#define INV_SQRT_N 0.0030070286f  // 1/sqrt(110592)

#define NOUT       (BATCH * NF * NM)       // 8192 complex elements
#define OUT_FLOATS (NOUT * 2)              // 16384

// reduction tree
#define R1_GROUPS  18             // stage-1 groups
#define R1_CH      8              // chunks per stage-1 group (18*8 = 144)

#define SZ_A   (BN * 16)
#define SZ_X   (BN * 3)
#define SZ_AW  (16 * 16)
#define SZ_XW  (3 * 256)

// SMEM layout (floats): aw[256] | x[2304] | A[12288]  => 59392 bytes
#define SMF_AW  0
#define SMF_X   256
#define SMF_A   (256 + 2304)
#define SMEM_BYTES ((256 + 2304 + 12288) * 4)

// ---------------- device scratch (no allocation allowed) ----------------
__device__ float g_part[NCHUNK * OUT_FLOATS];     // per-chunk planar partials (9.4 MB)
__device__ float g_p2[R1_GROUPS * OUT_FLOATS];    // stage-1 partials (1.2 MB)

// ---------------- helpers ----------------
__device__ __forceinline__ uint32_t tf32r(float f) {
    uint32_t r;
    asm("cvt.rna.tf32.f32 %0, %1;" : "=r"(r) : "f"(f));
    return r;
}
__device__ __forceinline__ void mma_tf32(float* d, const uint32_t* a, const uint32_t* b) {
    asm volatile(
        "mma.sync.aligned.m16n8k8.row.col.f32.tf32.tf32.f32 "
        "{%0,%1,%2,%3}, {%4,%5,%6,%7}, {%8,%9}, {%0,%1,%2,%3};"
        : "+f"(d[0]), "+f"(d[1]), "+f"(d[2]), "+f"(d[3])
        : "r"(a[0]), "r"(a[1]), "r"(a[2]), "r"(a[3]), "r"(b[0]), "r"(b[1]));
}

// ---------- fused kernel: stage + project + sincos + tf32 MMA ----------
// grid = (NCHUNK, BATCH), 256 threads. Warp w covers f in [w*32, w*32+32).
__global__ void __launch_bounds__(256, 2) spectral_main(const float* __restrict__ a,
                                                        const float* __restrict__ x,
                                                        const float* __restrict__ aw,
                                                        const float* __restrict__ xw) {
    extern __shared__ float sm[];
    float* s_aw = sm + SMF_AW;   // 16x16 row-major [i][m]
    float* s_x  = sm + SMF_X;    // 768 x 3 packed
    float* s_A  = sm + SMF_A;    // 768 x 16, tf32-rounded scaled coefficients

    const int tid  = threadIdx.x;
    const int lane = tid & 31;
    const int warp = tid >> 5;
    const int b    = blockIdx.y;
    const int chunk = blockIdx.x;
    const size_t pbase = (size_t)(b * NPTS + chunk * CHUNK);

    // ---- stage: aw, raw a-chunk (48KB), x-chunk (9KB), all coalesced ----
    s_aw[tid] = aw[tid];
    {
        const float4* ga = (const float4*)(a + pbase * 16);   // 3072 float4
        float4* sa4 = (float4*)s_A;
#pragma unroll
        for (int i = 0; i < 12; ++i) sa4[tid + 256 * i] = ga[tid + 256 * i];
        const float4* gx = (const float4*)(x + pbase * 3);    // 576 float4
        float4* sx4 = (float4*)s_x;
        for (int i = tid; i < 576; i += 256) sx4[i] = gx[i];
    }
    __syncthreads();

    // ---- in-place projection: A[p][m] = tf32(sum_i a[p][i]*aw[i][m] * inv_sqrt_n)
#pragma unroll
    for (int r = 0; r < 3; ++r) {
        int p = r * 256 + tid;
        float ai[16];
#pragma unroll
        for (int i = 0; i < 16; ++i) ai[i] = s_A[p * 16 + i];
        float o[16];
#pragma unroll
        for (int m = 0; m < 16; ++m) o[m] = 0.0f;
#pragma unroll
        for (int i = 0; i < 16; ++i)
#pragma unroll
            for (int m = 0; m < 16; ++m)
                o[m] = fmaf(ai[i], s_aw[i * 16 + m], o[m]);
#pragma unroll
        for (int m = 0; m < 16; ++m)
            s_A[p * 16 + m] = __uint_as_float(tf32r(o[m] * INV_SQRT_N));
    }
    __syncthreads();

    // ---- per-thread frequency weights (2*pi folded), 4 f's per thread ----
    const int fb = warp * 32 + (lane >> 2);
    float W[4][3];
#pragma unroll
    for (int j = 0; j < 4; ++j) {
        int f = fb + 8 * j;
        W[j][0] = TWO_PI_F * xw[f];
        W[j][1] = TWO_PI_F * xw[NF + f];
        W[j][2] = TWO_PI_F * xw[2 * NF + f];
    }

    float accR[2][2][4], accI[2][2][4];
#pragma unroll
    for (int i = 0; i < 2; ++i)
#pragma unroll
        for (int j = 0; j < 2; ++j)
#pragma unroll
            for (int k = 0; k < 4; ++k) { accR[i][j][k] = 0.0f; accI[i][j][k] = 0.0f; }

    const int kp = lane & 3;        // k-position within point-block
    const int m0 = lane >> 2;       // m channel for B fragment

    for (int pb = 0; pb < NPB; ++pb) {
        const int p0 = pb * 8 + kp;
        float xa0 = s_x[p0 * 3], xb0 = s_x[p0 * 3 + 1], xc0 = s_x[p0 * 3 + 2];
        float xa1 = s_x[(p0 + 4) * 3], xb1 = s_x[(p0 + 4) * 3 + 1], xc1 = s_x[(p0 + 4) * 3 + 2];

        float cv[8], sv[8];
#pragma unroll
        for (int j = 0; j < 4; ++j) {
            float ph0 = fmaf(xa0, W[j][0], fmaf(xb0, W[j][1], xc0 * W[j][2]));
            float ph1 = fmaf(xa1, W[j][0], fmaf(xb1, W[j][1], xc1 * W[j][2]));
            __sincosf(ph0, &sv[2 * j], &cv[2 * j]);
            __sincosf(ph1, &sv[2 * j + 1], &cv[2 * j + 1]);
        }

        uint32_t fc0[4] = { tf32r(cv[0]), tf32r(cv[2]), tf32r(cv[1]), tf32r(cv[3]) };
        uint32_t fs0[4] = { tf32r(sv[0]), tf32r(sv[2]), tf32r(sv[1]), tf32r(sv[3]) };
        uint32_t fc1[4] = { tf32r(cv[4]), tf32r(cv[6]), tf32r(cv[5]), tf32r(cv[7]) };
        uint32_t fs1[4] = { tf32r(sv[4]), tf32r(sv[6]), tf32r(sv[5]), tf32r(sv[7]) };

        uint32_t bm0[2] = { __float_as_uint(s_A[p0 * 16 + m0]),
                            __float_as_uint(s_A[(p0 + 4) * 16 + m0]) };
        uint32_t bm8[2] = { __float_as_uint(s_A[p0 * 16 + m0 + 8]),
                            __float_as_uint(s_A[(p0 + 4) * 16 + m0 + 8]) };

        mma_tf32(accR[0][0], fc0, bm0);  mma_tf32(accR[0][1], fc0, bm8);
        mma_tf32(accI[0][0], fs0, bm0);  mma_tf32(accI[0][1], fs0, bm8);
        mma_tf32(accR[1][0], fc1, bm0);  mma_tf32(accR[1][1], fc1, bm8);
        mma_tf32(accI[1][0], fs1, bm0);  mma_tf32(accI[1][1], fs1, bm8);
    }

    // ---- epilogue: C-fragment -> planar per-chunk partials ----
    float* basep = g_part + (size_t)chunk * OUT_FLOATS;
#pragma unroll
    for (int ft = 0; ft < 2; ++ft) {
#pragma unroll
        for (int mh = 0; mh < 2; ++mh) {
            int mcol = mh * 8 + 2 * kp;
#pragma unroll
            for (int rh = 0; rh < 2; ++rh) {
                int f = warp * 32 + ft * 16 + (lane >> 2) + rh * 8;
                size_t o = (size_t)(b * NF + f) * NM + mcol;
                float2 vr = make_float2(accR[ft][mh][2 * rh], accR[ft][mh][2 * rh + 1]);
                float2 vi = make_float2(-accI[ft][mh][2 * rh], -accI[ft][mh][2 * rh + 1]);
                *(float2*)(basep + o) = vr;              // real plane
                *(float2*)(basep + NOUT + o) = vi;       // imag plane
            }
        }
    }
}

// ---------- reduce stage 1: sum 8 chunks per group ----------
// grid = (OUT_FLOATS/256, R1_GROUPS)
__global__ void __launch_bounds__(256) reduce1_kernel(void) {
    int j = blockIdx.x * 256 + threadIdx.x;
    int c0 = blockIdx.y * R1_CH;
    float s = 0.0f;
#pragma unroll
    for (int c = 0; c < R1_CH; ++c)
        s += g_part[(size_t)(c0 + c) * OUT_FLOATS + j];
    g_p2[(size_t)blockIdx.y * OUT_FLOATS + j] = s;
}

// ---------- reduce stage 2: sum 18 groups, write planar output ----------
// grid = OUT_FLOATS/256 (imag half guarded by write_imag)
__global__ void __launch_bounds__(256) reduce2_kernel(float* __restrict__ out, int write_imag) {
    int j = blockIdx.x * 256 + threadIdx.x;
    float s = 0.0f;
#pragma unroll
    for (int g = 0; g < R1_GROUPS; ++g)
        s += g_p2[(size_t)g * OUT_FLOATS + j];
    if (j < NOUT) out[j] = s;
    else if (write_imag) out[j] = s;
}

extern "C" void kernel_launch(void* const* d_in, const int* in_sizes, int n_in,
                              void* d_out, int out_size) {
    const float* a  = nullptr;
    const float* x  = nullptr;
    const float* aw = nullptr;
    const float* xw = nullptr;
    for (int i = 0; i < n_in; ++i) {
        switch (in_sizes[i]) {
            case SZ_A:  a  = (const float*)d_in[i]; break;
            case SZ_X:  x  = (const float*)d_in[i]; break;
            case SZ_AW: aw = (const float*)d_in[i]; break;
            case SZ_XW: xw = (const float*)d_in[i]; break;
            default: break;
        }
    }
    float* out = (float*)d_out;
    int write_imag = (out_size >= OUT_FLOATS) ? 1 : 0;

    cudaFuncSetAttribute(spectral_main,
                         cudaFuncAttributeMaxDynamicSharedMemorySize, SMEM_BYTES);

    dim3 grid(NCHUNK, BATCH);
    spectral_main<<<grid, 256, SMEM_BYTES>>>(a, x, aw, xw);
    dim3 rg1(OUT_FLOATS / 256, R1_GROUPS);
    reduce1_kernel<<<rg1, 256>>>();
    reduce2_kernel<<<OUT_FLOATS / 256, 256>>>(out, write_imag);
}

// round 11
// speedup vs baseline: 3.8901x; 1.2409x over previous
#include <cuda_runtime.h>
#include <cstdint>

// ---------------- problem constants ----------------
#define BATCH   2
#define NPTS    110592            // 48^3
#define BN      (BATCH * NPTS)    // 221184
#define NF      256
#define NM      16
#define NCHUNK  144               // chunks per batch
#define CHUNK   768               // points per CTA
#define NPB     (CHUNK / 8)       // 96 point-blocks of 8
#define TWO_PI_F 6.283185307179586f
#define INV_SQRT_N 0.0030070286f  // 1/sqrt(110592)

#define NOUT       (BATCH * NF * NM)       // 8192 complex elements
#define OUT_FLOATS (NOUT * 2)              // 16384

// reduction tree
#define R1_GROUPS  18
#define R1_CH      8

#define SZ_A   (BN * 16)
#define SZ_X   (BN * 3)
#define SZ_AW  (16 * 16)
#define SZ_XW  (3 * 256)

// SMEM layout (floats): aw[256] | xraw[2304] | x4[3072] | A[12288]
#define SMF_AW  0
#define SMF_XR  256
#define SMF_X4  (256 + 2304)
#define SMF_A   (256 + 2304 + 3072)
#define SMEM_BYTES ((256 + 2304 + 3072 + 12288) * 4)   // 71680

// ---------------- device scratch (no allocation allowed) ----------------
__device__ float g_part[NCHUNK * OUT_FLOATS];     // per-chunk planar partials (9.4 MB)
__device__ float g_p2[R1_GROUPS * OUT_FLOATS];    // stage-1 partials (1.2 MB)

// ---------------- helpers ----------------
__device__ __forceinline__ uint32_t tf32r(float f) {
    uint32_t r;
    asm("cvt.rna.tf32.f32 %0, %1;" : "=r"(r) : "f"(f));
    return r;
}
__device__ __forceinline__ void mma_tf32(float* d, const uint32_t* a, const uint32_t* b) {
    asm volatile(
        "mma.sync.aligned.m16n8k8.row.col.f32.tf32.tf32.f32 "
        "{%0,%1,%2,%3}, {%4,%5,%6,%7}, {%8,%9}, {%0,%1,%2,%3};"
        : "+f"(d[0]), "+f"(d[1]), "+f"(d[2]), "+f"(d[3])
        : "r"(a[0]), "r"(a[1]), "r"(a[2]), "r"(a[3]), "r"(b[0]), "r"(b[1]));
}

// ---------- fused kernel: stage + project + sincos + tf32 MMA ----------
// grid = (NCHUNK, BATCH), 256 threads, 3 CTAs/SM target.
__global__ void __launch_bounds__(256, 3) spectral_main(const float* __restrict__ a,
                                                        const float* __restrict__ x,
                                                        const float* __restrict__ aw,
                                                        const float* __restrict__ xw) {
    extern __shared__ float sm[];
    float*  s_aw = sm + SMF_AW;    // 16x16 row-major [i][m]
    float*  s_xr = sm + SMF_XR;    // 768 x 3 raw
    float4* s_x4 = (float4*)(sm + SMF_X4);  // 768 x float4 (padded)
    float*  s_A  = sm + SMF_A;     // 768 x 16, tf32-rounded scaled coefficients

    const int tid  = threadIdx.x;
    const int lane = tid & 31;
    const int warp = tid >> 5;
    const int b    = blockIdx.y;
    const int chunk = blockIdx.x;
    const size_t pbase = (size_t)(b * NPTS + chunk * CHUNK);

    // ---- stage: aw, raw a-chunk (48KB), raw x-chunk (9KB), all coalesced ----
    s_aw[tid] = aw[tid];
    {
        const float4* ga = (const float4*)(a + pbase * 16);   // 3072 float4
        float4* sa4 = (float4*)s_A;
#pragma unroll
        for (int i = 0; i < 12; ++i) sa4[tid + 256 * i] = ga[tid + 256 * i];
        const float4* gx = (const float4*)(x + pbase * 3);    // 576 float4
        float4* sx4 = (float4*)s_xr;
        for (int i = tid; i < 576; i += 256) sx4[i] = gx[i];
    }
    __syncthreads();

    // ---- pad x to float4 (separate buffers, no hazard) ----
    {
        float r0 = s_xr[tid * 9 + 0], r1 = s_xr[tid * 9 + 1], r2 = s_xr[tid * 9 + 2];
        float r3 = s_xr[tid * 9 + 3], r4 = s_xr[tid * 9 + 4], r5 = s_xr[tid * 9 + 5];
        float r6 = s_xr[tid * 9 + 6], r7 = s_xr[tid * 9 + 7], r8 = s_xr[tid * 9 + 8];
        s_x4[tid * 3 + 0] = make_float4(r0, r1, r2, 0.0f);
        s_x4[tid * 3 + 1] = make_float4(r3, r4, r5, 0.0f);
        s_x4[tid * 3 + 2] = make_float4(r6, r7, r8, 0.0f);
    }

    // ---- in-place projection: A[p][m] = tf32(sum_i a[p][i]*aw[i][m] * inv_sqrt_n)
#pragma unroll
    for (int r = 0; r < 3; ++r) {
        int p = r * 256 + tid;
        float ai[16];
#pragma unroll
        for (int i = 0; i < 16; ++i) ai[i] = s_A[p * 16 + i];
        float o[16];
#pragma unroll
        for (int m = 0; m < 16; ++m) o[m] = 0.0f;
#pragma unroll
        for (int i = 0; i < 16; ++i)
#pragma unroll
            for (int m = 0; m < 16; ++m)
                o[m] = fmaf(ai[i], s_aw[i * 16 + m], o[m]);
#pragma unroll
        for (int m = 0; m < 16; ++m)
            s_A[p * 16 + m] = __uint_as_float(tf32r(o[m] * INV_SQRT_N));
    }
    __syncthreads();

    // ---- per-thread frequency weights (2*pi folded), 4 f's per thread ----
    const int fb = warp * 32 + (lane >> 2);
    float W[4][3];
#pragma unroll
    for (int j = 0; j < 4; ++j) {
        int f = fb + 8 * j;
        W[j][0] = TWO_PI_F * xw[f];
        W[j][1] = TWO_PI_F * xw[NF + f];
        W[j][2] = TWO_PI_F * xw[2 * NF + f];
    }

    float accR[2][2][4], accI[2][2][4];
#pragma unroll
    for (int i = 0; i < 2; ++i)
#pragma unroll
        for (int j = 0; j < 2; ++j)
#pragma unroll
            for (int k = 0; k < 4; ++k) { accR[i][j][k] = 0.0f; accI[i][j][k] = 0.0f; }

    const int kp = lane & 3;        // k-position within point-block
    const int m0 = lane >> 2;       // m channel for B fragment

    for (int pb = 0; pb < NPB; ++pb) {
        const int p0 = pb * 8 + kp;
        float4 xv0 = s_x4[p0];          // LDS.128
        float4 xv1 = s_x4[p0 + 4];

        float cv[8], sv[8];             // [j*2 + psel]
#pragma unroll
        for (int j = 0; j < 4; ++j) {
            float ph0 = fmaf(xv0.x, W[j][0], fmaf(xv0.y, W[j][1], xv0.z * W[j][2]));
            float ph1 = fmaf(xv1.x, W[j][0], fmaf(xv1.y, W[j][1], xv1.z * W[j][2]));
            __sincosf(ph0, &sv[2 * j], &cv[2 * j]);
            __sincosf(ph1, &sv[2 * j + 1], &cv[2 * j + 1]);
        }

        // A fragments: raw fp32 bits (tf32 MMA HW ignores low 13 mantissa bits)
        uint32_t fc0[4] = { __float_as_uint(cv[0]), __float_as_uint(cv[2]),
                            __float_as_uint(cv[1]), __float_as_uint(cv[3]) };
        uint32_t fs0[4] = { __float_as_uint(sv[0]), __float_as_uint(sv[2]),
                            __float_as_uint(sv[1]), __float_as_uint(sv[3]) };
        uint32_t fc1[4] = { __float_as_uint(cv[4]), __float_as_uint(cv[6]),
                            __float_as_uint(cv[5]), __float_as_uint(cv[7]) };
        uint32_t fs1[4] = { __float_as_uint(sv[4]), __float_as_uint(sv[6]),
                            __float_as_uint(sv[5]), __float_as_uint(sv[7]) };

        uint32_t bm0[2] = { __float_as_uint(s_A[p0 * 16 + m0]),
                            __float_as_uint(s_A[(p0 + 4) * 16 + m0]) };
        uint32_t bm8[2] = { __float_as_uint(s_A[p0 * 16 + m0 + 8]),
                            __float_as_uint(s_A[(p0 + 4) * 16 + m0 + 8]) };

        mma_tf32(accR[0][0], fc0, bm0);  mma_tf32(accR[0][1], fc0, bm8);
        mma_tf32(accI[0][0], fs0, bm0);  mma_tf32(accI[0][1], fs0, bm8);
        mma_tf32(accR[1][0], fc1, bm0);  mma_tf32(accR[1][1], fc1, bm8);
        mma_tf32(accI[1][0], fs1, bm0);  mma_tf32(accI[1][1], fs1, bm8);
    }

    // ---- epilogue: C-fragment -> planar per-chunk partials ----
    float* basep = g_part + (size_t)chunk * OUT_FLOATS;
#pragma unroll
    for (int ft = 0; ft < 2; ++ft) {
#pragma unroll
        for (int mh = 0; mh < 2; ++mh) {
            int mcol = mh * 8 + 2 * kp;
#pragma unroll
            for (int rh = 0; rh < 2; ++rh) {
                int f = warp * 32 + ft * 16 + (lane >> 2) + rh * 8;
                size_t o = (size_t)(b * NF + f) * NM + mcol;
                float2 vr = make_float2(accR[ft][mh][2 * rh], accR[ft][mh][2 * rh + 1]);
                float2 vi = make_float2(-accI[ft][mh][2 * rh], -accI[ft][mh][2 * rh + 1]);
                *(float2*)(basep + o) = vr;              // real plane
                *(float2*)(basep + NOUT + o) = vi;       // imag plane
            }
        }
    }
}

// ---------- reduce stage 1: sum 8 chunks per group ----------
__global__ void __launch_bounds__(256) reduce1_kernel(void) {
    int j = blockIdx.x * 256 + threadIdx.x;
    int c0 = blockIdx.y * R1_CH;
    float s = 0.0f;
#pragma unroll
    for (int c = 0; c < R1_CH; ++c)
        s += g_part[(size_t)(c0 + c) * OUT_FLOATS + j];
    g_p2[(size_t)blockIdx.y * OUT_FLOATS + j] = s;
}

// ---------- reduce stage 2: sum 18 groups, write planar output ----------
__global__ void __launch_bounds__(256) reduce2_kernel(float* __restrict__ out, int write_imag) {
    int j = blockIdx.x * 256 + threadIdx.x;
    float s = 0.0f;
#pragma unroll
    for (int g = 0; g < R1_GROUPS; ++g)
        s += g_p2[(size_t)g * OUT_FLOATS + j];
    if (j < NOUT) out[j] = s;
    else if (write_imag) out[j] = s;
}

extern "C" void kernel_launch(void* const* d_in, const int* in_sizes, int n_in,
                              void* d_out, int out_size) {
    const float* a  = nullptr;
    const float* x  = nullptr;
    const float* aw = nullptr;
    const float* xw = nullptr;
    for (int i = 0; i < n_in; ++i) {
        switch (in_sizes[i]) {
            case SZ_A:  a  = (const float*)d_in[i]; break;
            case SZ_X:  x  = (const float*)d_in[i]; break;
            case SZ_AW: aw = (const float*)d_in[i]; break;
            case SZ_XW: xw = (const float*)d_in[i]; break;
            default: break;
        }
    }
    float* out = (float*)d_out;
    int write_imag = (out_size >= OUT_FLOATS) ? 1 : 0;

    cudaFuncSetAttribute(spectral_main,
                         cudaFuncAttributeMaxDynamicSharedMemorySize, SMEM_BYTES);

    dim3 grid(NCHUNK, BATCH);
    spectral_main<<<grid, 256, SMEM_BYTES>>>(a, x, aw, xw);
    dim3 rg1(OUT_FLOATS / 256, R1_GROUPS);
    reduce1_kernel<<<rg1, 256>>>();
    reduce2_kernel<<<OUT_FLOATS / 256, 256>>>(out, write_imag);
}

// round 12
// speedup vs baseline: 4.0547x; 1.0423x over previous
#include <cuda_runtime.h>
#include <cstdint>

// ---------------- problem constants ----------------
#define BATCH   2
#define NPTS    110592            // 48^3
#define BN      (BATCH * NPTS)    // 221184
#define NF      256
#define NM      16
#define NCHUNK  216               // chunks per batch
#define CHUNK   512               // points per CTA (216 * 512 = 110592)
#define NPB     (CHUNK / 8)       // 64 point-blocks of 8
#define TWO_PI_F 6.283185307179586f
#define INV_SQRT_N 0.0030070286f  // 1/sqrt(110592)

#define NOUT       (BATCH * NF * NM)       // 8192 complex elements
#define OUT_FLOATS (NOUT * 2)              // 16384

// reduction tree: 216 = 27 * 8
#define R1_GROUPS  27
#define R1_CH      8

#define SZ_A   (BN * 16)
#define SZ_X   (BN * 3)
#define SZ_AW  (16 * 16)
#define SZ_XW  (3 * 256)

// SMEM layout (floats): aw[256] | xraw[1536] | x4[2048] | A[8192]
#define SMF_AW  0
#define SMF_XR  256
#define SMF_X4  (256 + 1536)
#define SMF_A   (256 + 1536 + 2048)
#define SMEM_BYTES ((256 + 1536 + 2048 + 8192) * 4)   // 48128

// ---------------- device scratch (no allocation allowed) ----------------
__device__ float g_part[NCHUNK * OUT_FLOATS];     // per-chunk planar partials (14.2 MB)
__device__ float g_p2[R1_GROUPS * OUT_FLOATS];    // stage-1 partials (1.8 MB)

// ---------------- helpers ----------------
__device__ __forceinline__ uint32_t tf32r(float f) {
    uint32_t r;
    asm("cvt.rna.tf32.f32 %0, %1;" : "=r"(r) : "f"(f));
    return r;
}
__device__ __forceinline__ void mma_tf32(float* d, const uint32_t* a, const uint32_t* b) {
    asm volatile(
        "mma.sync.aligned.m16n8k8.row.col.f32.tf32.tf32.f32 "
        "{%0,%1,%2,%3}, {%4,%5,%6,%7}, {%8,%9}, {%0,%1,%2,%3};"
        : "+f"(d[0]), "+f"(d[1]), "+f"(d[2]), "+f"(d[3])
        : "r"(a[0]), "r"(a[1]), "r"(a[2]), "r"(a[3]), "r"(b[0]), "r"(b[1]));
}

// ---------- fused kernel: stage + project + sincos + tf32 MMA ----------
// grid = (NCHUNK, BATCH), 256 threads, 3 CTAs/SM.
__global__ void __launch_bounds__(256, 3) spectral_main(const float* __restrict__ a,
                                                        const float* __restrict__ x,
                                                        const float* __restrict__ aw,
                                                        const float* __restrict__ xw) {
    extern __shared__ float sm[];
    float*  s_aw = sm + SMF_AW;    // 16x16 row-major [i][m]
    float*  s_xr = sm + SMF_XR;    // 512 x 3 raw
    float4* s_x4 = (float4*)(sm + SMF_X4);  // 512 x float4 (padded)
    float*  s_A  = sm + SMF_A;     // 512 x 16, tf32-rounded scaled coefficients

    const int tid  = threadIdx.x;
    const int lane = tid & 31;
    const int warp = tid >> 5;
    const int b    = blockIdx.y;
    const int chunk = blockIdx.x;
    const size_t pbase = (size_t)(b * NPTS + chunk * CHUNK);

    // ---- stage: aw, raw a-chunk (32KB), raw x-chunk (6KB), all coalesced ----
    s_aw[tid] = aw[tid];
    {
        const float4* ga = (const float4*)(a + pbase * 16);   // 2048 float4
        float4* sa4 = (float4*)s_A;
#pragma unroll
        for (int i = 0; i < 8; ++i) sa4[tid + 256 * i] = ga[tid + 256 * i];
        const float4* gx = (const float4*)(x + pbase * 3);    // 384 float4
        float4* sx4 = (float4*)s_xr;
        for (int i = tid; i < 384; i += 256) sx4[i] = gx[i];
    }
    __syncthreads();

    // ---- pad x to float4: thread pads points 2*tid and 2*tid+1 ----
    {
        float r0 = s_xr[tid * 6 + 0], r1 = s_xr[tid * 6 + 1], r2 = s_xr[tid * 6 + 2];
        float r3 = s_xr[tid * 6 + 3], r4 = s_xr[tid * 6 + 4], r5 = s_xr[tid * 6 + 5];
        s_x4[tid * 2 + 0] = make_float4(r0, r1, r2, 0.0f);
        s_x4[tid * 2 + 1] = make_float4(r3, r4, r5, 0.0f);
    }

    // ---- in-place projection: A[p][m] = tf32(sum_i a[p][i]*aw[i][m] * inv_sqrt_n)
#pragma unroll
    for (int r = 0; r < 2; ++r) {
        int p = r * 256 + tid;
        float ai[16];
#pragma unroll
        for (int i = 0; i < 16; ++i) ai[i] = s_A[p * 16 + i];
        float o[16];
#pragma unroll
        for (int m = 0; m < 16; ++m) o[m] = 0.0f;
#pragma unroll
        for (int i = 0; i < 16; ++i)
#pragma unroll
            for (int m = 0; m < 16; ++m)
                o[m] = fmaf(ai[i], s_aw[i * 16 + m], o[m]);
#pragma unroll
        for (int m = 0; m < 16; ++m)
            s_A[p * 16 + m] = __uint_as_float(tf32r(o[m] * INV_SQRT_N));
    }
    __syncthreads();

    // ---- per-thread frequency weights (2*pi folded), 4 f's per thread ----
    const int fb = warp * 32 + (lane >> 2);
    float W[4][3];
#pragma unroll
    for (int j = 0; j < 4; ++j) {
        int f = fb + 8 * j;
        W[j][0] = TWO_PI_F * xw[f];
        W[j][1] = TWO_PI_F * xw[NF + f];
        W[j][2] = TWO_PI_F * xw[2 * NF + f];
    }

    float accR[2][2][4], accI[2][2][4];
#pragma unroll
    for (int i = 0; i < 2; ++i)
#pragma unroll
        for (int j = 0; j < 2; ++j)
#pragma unroll
            for (int k = 0; k < 4; ++k) { accR[i][j][k] = 0.0f; accI[i][j][k] = 0.0f; }

    const int kp = lane & 3;        // k-position within point-block
    const int m0 = lane >> 2;       // m channel for B fragment

    for (int pb = 0; pb < NPB; ++pb) {
        const int p0 = pb * 8 + kp;
        float4 xv0 = s_x4[p0];          // LDS.128
        float4 xv1 = s_x4[p0 + 4];

        float cv[8], sv[8];             // [j*2 + psel]
#pragma unroll
        for (int j = 0; j < 4; ++j) {
            float ph0 = fmaf(xv0.x, W[j][0], fmaf(xv0.y, W[j][1], xv0.z * W[j][2]));
            float ph1 = fmaf(xv1.x, W[j][0], fmaf(xv1.y, W[j][1], xv1.z * W[j][2]));
            __sincosf(ph0, &sv[2 * j], &cv[2 * j]);
            __sincosf(ph1, &sv[2 * j + 1], &cv[2 * j + 1]);
        }

        // A fragments: raw fp32 bits (tf32 MMA HW truncates low mantissa bits)
        uint32_t fc0[4] = { __float_as_uint(cv[0]), __float_as_uint(cv[2]),
                            __float_as_uint(cv[1]), __float_as_uint(cv[3]) };
        uint32_t fs0[4] = { __float_as_uint(sv[0]), __float_as_uint(sv[2]),
                            __float_as_uint(sv[1]), __float_as_uint(sv[3]) };
        uint32_t fc1[4] = { __float_as_uint(cv[4]), __float_as_uint(cv[6]),
                            __float_as_uint(cv[5]), __float_as_uint(cv[7]) };
        uint32_t fs1[4] = { __float_as_uint(sv[4]), __float_as_uint(sv[6]),
                            __float_as_uint(sv[5]), __float_as_uint(sv[7]) };

        uint32_t bm0[2] = { __float_as_uint(s_A[p0 * 16 + m0]),
                            __float_as_uint(s_A[(p0 + 4) * 16 + m0]) };
        uint32_t bm8[2] = { __float_as_uint(s_A[p0 * 16 + m0 + 8]),
                            __float_as_uint(s_A[(p0 + 4) * 16 + m0 + 8]) };

        mma_tf32(accR[0][0], fc0, bm0);  mma_tf32(accR[0][1], fc0, bm8);
        mma_tf32(accI[0][0], fs0, bm0);  mma_tf32(accI[0][1], fs0, bm8);
        mma_tf32(accR[1][0], fc1, bm0);  mma_tf32(accR[1][1], fc1, bm8);
        mma_tf32(accI[1][0], fs1, bm0);  mma_tf32(accI[1][1], fs1, bm8);
    }

    // ---- epilogue: C-fragment -> planar per-chunk partials ----
    float* basep = g_part + (size_t)chunk * OUT_FLOATS;
#pragma unroll
    for (int ft = 0; ft < 2; ++ft) {
#pragma unroll
        for (int mh = 0; mh < 2; ++mh) {
            int mcol = mh * 8 + 2 * kp;
#pragma unroll
            for (int rh = 0; rh < 2; ++rh) {
                int f = warp * 32 + ft * 16 + (lane >> 2) + rh * 8;
                size_t o = (size_t)(b * NF + f) * NM + mcol;
                float2 vr = make_float2(accR[ft][mh][2 * rh], accR[ft][mh][2 * rh + 1]);
                float2 vi = make_float2(-accI[ft][mh][2 * rh], -accI[ft][mh][2 * rh + 1]);
                *(float2*)(basep + o) = vr;              // real plane
                *(float2*)(basep + NOUT + o) = vi;       // imag plane
            }
        }
    }
}

// ---------- reduce stage 1: sum 8 chunks per group ----------
__global__ void __launch_bounds__(256) reduce1_kernel(void) {
    int j = blockIdx.x * 256 + threadIdx.x;
    int c0 = blockIdx.y * R1_CH;
    float s = 0.0f;
#pragma unroll
    for (int c = 0; c < R1_CH; ++c)
        s += g_part[(size_t)(c0 + c) * OUT_FLOATS + j];
    g_p2[(size_t)blockIdx.y * OUT_FLOATS + j] = s;
}

// ---------- reduce stage 2: sum 27 groups, write planar output ----------
__global__ void __launch_bounds__(256) reduce2_kernel(float* __restrict__ out, int write_imag) {
    int j = blockIdx.x * 256 + threadIdx.x;
    float s = 0.0f;
#pragma unroll
    for (int g = 0; g < R1_GROUPS; ++g)
        s += g_p2[(size_t)g * OUT_FLOATS + j];
    if (j < NOUT) out[j] = s;
    else if (write_imag) out[j] = s;
}

extern "C" void kernel_launch(void* const* d_in, const int* in_sizes, int n_in,
                              void* d_out, int out_size) {
    const float* a  = nullptr;
    const float* x  = nullptr;
    const float* aw = nullptr;
    const float* xw = nullptr;
    for (int i = 0; i < n_in; ++i) {
        switch (in_sizes[i]) {
            case SZ_A:  a  = (const float*)d_in[i]; break;
            case SZ_X:  x  = (const float*)d_in[i]; break;
            case SZ_AW: aw = (const float*)d_in[i]; break;
            case SZ_XW: xw = (const float*)d_in[i]; break;
            default: break;
        }
    }
    float* out = (float*)d_out;
    int write_imag = (out_size >= OUT_FLOATS) ? 1 : 0;

    cudaFuncSetAttribute(spectral_main,
                         cudaFuncAttributeMaxDynamicSharedMemorySize, SMEM_BYTES);

    dim3 grid(NCHUNK, BATCH);
    spectral_main<<<grid, 256, SMEM_BYTES>>>(a, x, aw, xw);
    dim3 rg1(OUT_FLOATS / 256, R1_GROUPS);
    reduce1_kernel<<<rg1, 256>>>();
    reduce2_kernel<<<OUT_FLOATS / 256, 256>>>(out, write_imag);
}